// round 2
// baseline (speedup 1.0000x reference)
#include <cuda_runtime.h>
#include <math_constants.h>

#define V  50000
#define E  300
#define H  256
#define R  2048
#define L0 128
#define LR 64
#define S  2049          // 1 + R
#define G3 768           // 3*H

// ---------------- scratch (device globals; no allocation allowed) -------------
__device__ float g_X[S * E];                 // summed embeddings, row 0 = orig
__device__ float g_gi_f[S * G3];             // Wih_f @ X[t] + bih_f
__device__ float g_gi_b[S * G3];             // Wih_b @ X[S-1-t] + bih_b
__device__ float g_ys_f[S * H];              // forward hidden states
__device__ float g_ys_b[S * H];              // backward hidden states (already re-reversed)
__device__ unsigned long long g_h64[2 * H];  // tagged h broadcast: [dir*H + i]

// ---------------- kernel 0: reset tag words (needed every graph replay) -------
__global__ void zero_tags_kernel() {
    int tid = threadIdx.x;
    if (tid < 2 * H) g_h64[tid] = 0ULL;
}

// ---------------- kernel 1: embedding sums -> X -------------------------------
__global__ void embed_kernel(const int* __restrict__ orig,
                             const int* __restrict__ reply,
                             const int* __restrict__ lens,
                             const float* __restrict__ embed) {
    int t = blockIdx.x;          // 0..S-1
    int e = threadIdx.x;         // blockDim = 320, guard to 300
    if (e >= E) return;
    float acc = 0.f;
    if (t == 0) {
        #pragma unroll 4
        for (int l = 0; l < L0; ++l) {
            int tok = orig[l];
            acc += embed[(long long)tok * E + e];
        }
    } else {
        int r = t - 1;
        int len = lens[r];
        const int* rt = reply + r * LR;
        for (int l = 0; l < len; ++l) {
            int tok = rt[l];
            acc += embed[(long long)tok * E + e];
        }
    }
    g_X[t * E + e] = acc;
}

// ---------------- kernel 2: gi GEMMs (both directions) ------------------------
// out[t, row] = bias[row] + sum_k W[row,k] * X[tsrc, k],  tsrc = t (fwd) / S-1-t (bwd)
#define TT 32
#define RR 64
#define KC 32
__global__ void gi_kernel(const float* __restrict__ Wf, const float* __restrict__ bf,
                          const float* __restrict__ Wb, const float* __restrict__ bb) {
    int dir = blockIdx.z;
    const float* W    = dir ? Wb : Wf;
    const float* bias = dir ? bb : bf;
    float* out        = dir ? g_gi_b : g_gi_f;
    int t0 = blockIdx.x * TT;
    int r0 = blockIdx.y * RR;

    __shared__ float Xs[TT][KC];
    __shared__ float Ws[RR][KC + 1];

    int tid = threadIdx.x;     // 256
    int r  = tid % RR;         // output row within tile (coalesced stores)
    int tg = tid / RR;         // 0..3, each handles 8 t's

    float acc[8];
    #pragma unroll
    for (int j = 0; j < 8; ++j) acc[j] = 0.f;

    for (int kk = 0; kk < E; kk += KC) {
        for (int i = tid; i < RR * KC; i += 256) {
            int rr = i / KC, k = i % KC;
            Ws[rr][k] = (kk + k < E) ? W[(r0 + rr) * E + kk + k] : 0.f;
        }
        for (int i = tid; i < TT * KC; i += 256) {
            int ttl = i / KC, k = i % KC;
            int t = t0 + ttl;
            float v = 0.f;
            if (t < S && kk + k < E) {
                int tsrc = dir ? (S - 1 - t) : t;
                v = g_X[tsrc * E + kk + k];
            }
            Xs[ttl][k] = v;
        }
        __syncthreads();
        #pragma unroll
        for (int k = 0; k < KC; ++k) {
            float wv = Ws[r][k];
            #pragma unroll
            for (int j = 0; j < 8; ++j)
                acc[j] += wv * Xs[tg * 8 + j][k];
        }
        __syncthreads();
    }
    float bv = bias[r0 + r];
    #pragma unroll
    for (int j = 0; j < 8; ++j) {
        int t = t0 + tg * 8 + j;
        if (t < S) out[t * G3 + r0 + r] = acc[j] + bv;
    }
}

// ---------------- kernel 3: the two GRU recurrences ---------------------------
// 32 CTAs per direction; CTA c owns h-dims [c*8, c*8+8).
// Warp w (0..23): gate g = w/8, local dim ld = w%8 -> Whh row = g*256 + c*8 + ld.
// Lane l holds Whh[row, 8l .. 8l+7] in registers (weights never re-read).
// Cross-CTA h exchange: 64-bit word = (t+1)<<32 | float bits, polled with == tag.
__global__ void __launch_bounds__(768, 1)
gru_kernel(const float* __restrict__ Whh_f, const float* __restrict__ bhh_f,
           const float* __restrict__ Whh_b, const float* __restrict__ bhh_b) {
    int cta = blockIdx.x;     // 0..63
    int dir = cta >> 5;
    int c   = cta & 31;
    const float* Whh = dir ? Whh_b : Whh_f;
    const float* bhh = dir ? bhh_b : bhh_f;
    const float* gi  = dir ? g_gi_b : g_gi_f;
    float* ys        = dir ? g_ys_b : g_ys_f;
    volatile unsigned long long* h64 = g_h64 + dir * H;

    int tid  = threadIdx.x;
    int w    = tid >> 5;        // 0..23
    int lane = tid & 31;
    int gate = w >> 3;          // 0=r, 1=z, 2=n
    int ld   = w & 7;
    int i    = c * 8 + ld;      // this warp's h-dim
    int row  = gate * H + i;    // Whh row

    // resident weights
    const float* wr = Whh + (long long)row * H + lane * 8;
    float4 wa = *(const float4*)(wr);
    float4 wb = *(const float4*)(wr + 4);
    float brow = bhh[row];

    __shared__ float sh_h[H];
    __shared__ float s_gh[24];

    if (tid < H) sh_h[tid] = 0.f;
    __syncthreads();

    for (int t = 0; t < S; ++t) {
        // prefetch gi for the combine (threads 0..7), latency hidden under dot
        float gir = 0.f, giz = 0.f, gin = 0.f;
        if (tid < 8) {
            int ii = c * 8 + tid;
            const float* gp = gi + t * G3;
            gir = gp[ii];
            giz = gp[H + ii];
            gin = gp[2 * H + ii];
        }

        // partial dot: 8 resident weights x 8 h values from smem
        const float* hp = sh_h + lane * 8;
        float4 ha = *(const float4*)(hp);
        float4 hb = *(const float4*)(hp + 4);
        float p = wa.x * ha.x + wa.y * ha.y + wa.z * ha.z + wa.w * ha.w
                + wb.x * hb.x + wb.y * hb.y + wb.z * hb.z + wb.w * hb.w;
        p += __shfl_down_sync(0xffffffffu, p, 16);
        p += __shfl_down_sync(0xffffffffu, p, 8);
        p += __shfl_down_sync(0xffffffffu, p, 4);
        p += __shfl_down_sync(0xffffffffu, p, 2);
        p += __shfl_down_sync(0xffffffffu, p, 1);
        if (lane == 0) s_gh[w] = p + brow;     // gh = Whh@h + bhh (per row)
        __syncthreads();

        // gate combine on 8 threads
        if (tid < 8) {
            int ii = c * 8 + tid;
            float rr = 1.f / (1.f + expf(-(gir + s_gh[tid])));
            float zz = 1.f / (1.f + expf(-(giz + s_gh[8 + tid])));
            float nn = tanhf(gin + rr * s_gh[16 + tid]);
            float hn = (1.f - zz) * nn + zz * sh_h[ii];
            int trow = dir ? (S - 1 - t) : t;
            ys[trow * H + ii] = hn;
            unsigned long long tagged =
                ((unsigned long long)(unsigned)(t + 1) << 32) |
                (unsigned long long)__float_as_uint(hn);
            h64[ii] = tagged;                  // volatile 64-bit: flag+data atomic
        }
        __syncthreads();                       // all reads of old sh_h complete

        // gather full h_{t+1} (256 dims) from all CTAs of this direction
        if (tid < H) {
            unsigned want = (unsigned)(t + 1);
            unsigned long long v;
            do { v = h64[tid]; } while ((unsigned)(v >> 32) != want);
            sh_h[tid] = __uint_as_float((unsigned)(v & 0xffffffffULL));
        }
        __syncthreads();
    }
}

// ---------------- kernel 4: output projection --------------------------------
// out[t, j] = bl[j] + sum_{k<256} ys_f[t,k]*Wl[j,k] + sum_{k<256} ys_b[t,k]*Wl[j,256+k]
__global__ void outproj_kernel(const float* __restrict__ Wl,
                               const float* __restrict__ bl,
                               float* __restrict__ outbuf) {
    int t0 = blockIdx.x * TT;
    int j0 = blockIdx.y * RR;
    __shared__ float As[TT][KC];
    __shared__ float Ws[RR][KC + 1];
    int tid = threadIdx.x;
    int r  = tid % RR;
    int tg = tid / RR;
    float acc[8];
    #pragma unroll
    for (int j = 0; j < 8; ++j) acc[j] = 0.f;

    for (int kk = 0; kk < 2 * H; kk += KC) {
        const float* ysrc = (kk < H) ? g_ys_f : g_ys_b;
        int kbase = (kk < H) ? kk : (kk - H);
        for (int i = tid; i < RR * KC; i += 256) {
            int rr = i / KC, k = i % KC;
            Ws[rr][k] = Wl[(j0 + rr) * (2 * H) + kk + k];
        }
        for (int i = tid; i < TT * KC; i += 256) {
            int ttl = i / KC, k = i % KC;
            int t = t0 + ttl;
            As[ttl][k] = (t < S) ? ysrc[t * H + kbase + k] : 0.f;
        }
        __syncthreads();
        #pragma unroll
        for (int k = 0; k < KC; ++k) {
            float wv = Ws[r][k];
            #pragma unroll
            for (int j = 0; j < 8; ++j)
                acc[j] += wv * As[tg * 8 + j][k];
        }
        __syncthreads();
    }
    float bv = bl[j0 + r];
    #pragma unroll
    for (int j = 0; j < 8; ++j) {
        int t = t0 + tg * 8 + j;
        if (t < S) outbuf[t * H + j0 + r] = acc[j] + bv;
    }
}

// ---------------- kernel 5: attention + final head (single block) -------------
__global__ void attn_kernel(const float* __restrict__ outbuf,
                            const float* __restrict__ Wo,
                            const float* __restrict__ bo,
                            const float* __restrict__ label,
                            float* __restrict__ tail) {
    __shared__ float s_hsum[H];
    __shared__ float s_w[S];
    __shared__ float s_red[32];
    __shared__ float s_ctx[4][H];

    int tid = threadIdx.x;     // 1024
    int wp  = tid >> 5;
    int ln  = tid & 31;

    if (tid < H) s_hsum[tid] = g_ys_f[(S - 1) * H + tid] + g_ys_b[tid];
    __syncthreads();

    // scores[t] = output[t] . hsum   (one warp per row, coalesced)
    for (int t = wp; t < S; t += 32) {
        const float* o = outbuf + t * H;
        float s = 0.f;
        #pragma unroll
        for (int k = ln; k < H; k += 32) s += o[k] * s_hsum[k];
        s += __shfl_down_sync(0xffffffffu, s, 16);
        s += __shfl_down_sync(0xffffffffu, s, 8);
        s += __shfl_down_sync(0xffffffffu, s, 4);
        s += __shfl_down_sync(0xffffffffu, s, 2);
        s += __shfl_down_sync(0xffffffffu, s, 1);
        if (ln == 0) s_w[t] = s;
    }
    __syncthreads();

    // block max
    float m = -CUDART_INF_F;
    for (int t = tid; t < S; t += 1024) m = fmaxf(m, s_w[t]);
    for (int off = 16; off >= 1; off >>= 1)
        m = fmaxf(m, __shfl_down_sync(0xffffffffu, m, off));
    if (ln == 0) s_red[wp] = m;
    __syncthreads();
    if (tid < 32) {
        float mm = s_red[tid];
        for (int off = 16; off >= 1; off >>= 1)
            mm = fmaxf(mm, __shfl_down_sync(0xffffffffu, mm, off));
        if (tid == 0) s_red[0] = mm;
    }
    __syncthreads();
    float M = s_red[0];
    __syncthreads();

    // exp + block sum
    float lsum = 0.f;
    for (int t = tid; t < S; t += 1024) {
        float e = expf(s_w[t] - M);
        s_w[t] = e;
        lsum += e;
    }
    for (int off = 16; off >= 1; off >>= 1)
        lsum += __shfl_down_sync(0xffffffffu, lsum, off);
    if (ln == 0) s_red[wp] = lsum;
    __syncthreads();
    if (tid < 32) {
        float ss = s_red[tid];
        for (int off = 16; off >= 1; off >>= 1)
            ss += __shfl_down_sync(0xffffffffu, ss, off);
        if (tid == 0) s_red[0] = ss;
    }
    __syncthreads();
    float SUM = s_red[0];

    // ctx[j] = (sum_t w[t] * output[t,j]) / SUM
    int j    = tid & 255;
    int part = tid >> 8;       // 0..3
    float cacc = 0.f;
    #pragma unroll 4
    for (int t = part; t < S; t += 4) cacc += s_w[t] * outbuf[t * H + j];
    s_ctx[part][j] = cacc;
    __syncthreads();

    if (tid < H) {
        float cj = (s_ctx[0][tid] + s_ctx[1][tid] + s_ctx[2][tid] + s_ctx[3][tid]) / SUM;
        s_hsum[tid] = cj * Wo[tid];   // reuse buffer: per-dim product with Wo
    }
    __syncthreads();

    if (tid < 32) {
        float a = 0.f;
        #pragma unroll
        for (int q = 0; q < 8; ++q) a += s_hsum[tid + q * 32];
        for (int off = 16; off >= 1; off >>= 1)
            a += __shfl_down_sync(0xffffffffu, a, off);
        if (tid == 0) {
            float res = 1.f / (1.f + expf(-(a + bo[0])));
            float d = label[0] - res;
            tail[0] = d * d;   // loss
            tail[1] = res;     // result
        }
    }
}

// ---------------- launch ------------------------------------------------------
extern "C" void kernel_launch(void* const* d_in, const int* in_sizes, int n_in,
                              void* d_out, int out_size) {
    const int*   orig   = (const int*)d_in[0];
    const int*   reply  = (const int*)d_in[1];
    const int*   lens   = (const int*)d_in[2];
    const float* label  = (const float*)d_in[3];
    const float* embed  = (const float*)d_in[4];
    const float* Wih_f  = (const float*)d_in[5];
    const float* Whh_f  = (const float*)d_in[6];
    const float* bih_f  = (const float*)d_in[7];
    const float* bhh_f  = (const float*)d_in[8];
    const float* Wih_b  = (const float*)d_in[9];
    const float* Whh_b  = (const float*)d_in[10];
    const float* bih_b  = (const float*)d_in[11];
    const float* bhh_b  = (const float*)d_in[12];
    const float* Wl     = (const float*)d_in[13];
    const float* bl     = (const float*)d_in[14];
    const float* Wo     = (const float*)d_in[15];
    const float* bo     = (const float*)d_in[16];
    float* out = (float*)d_out;

    zero_tags_kernel<<<1, 512>>>();
    embed_kernel<<<S, 320>>>(orig, reply, lens, embed);

    dim3 gi_grid((S + TT - 1) / TT, G3 / RR, 2);   // 65 x 12 x 2
    gi_kernel<<<gi_grid, 256>>>(Wih_f, bih_f, Wih_b, bih_b);

    gru_kernel<<<64, 768>>>(Whh_f, bhh_f, Whh_b, bhh_b);

    dim3 op_grid((S + TT - 1) / TT, H / RR);       // 65 x 4
    outproj_kernel<<<op_grid, 256>>>(Wl, bl, out);

    attn_kernel<<<1, 1024>>>(out, Wo, bo, label, out + S * H);
}

// round 3
// speedup vs baseline: 2.0288x; 2.0288x over previous
#include <cuda_runtime.h>
#include <math_constants.h>

#define V  50000
#define E  300
#define H  256
#define R  2048
#define L0 128
#define LR 64
#define S  2049          // 1 + R
#define G3 768           // 3*H

#define NC   8           // CTAs per cluster (one cluster per direction)
#define DPC  32          // h-dims per CTA
#define NW   24          // warps per CTA (one warp per 4 rows; 96 rows/CTA)

// ---------------- scratch (device globals; no allocation allowed) -------------
__device__ float g_X[S * E];
__device__ float g_gi_f[S * G3];
__device__ float g_gi_b[S * G3];
__device__ float g_ys_f[S * H];
__device__ float g_ys_b[S * H];

// ---------------- small PTX helpers ------------------------------------------
__device__ __forceinline__ unsigned long long pk2(float lo, float hi) {
    unsigned long long r;
    asm("mov.b64 %0, {%1, %2};" : "=l"(r) : "f"(lo), "f"(hi));
    return r;
}
__device__ __forceinline__ float unpk_sum(unsigned long long v) {
    float a, b;
    asm("mov.b64 {%0, %1}, %2;" : "=f"(a), "=f"(b) : "l"(v));
    return a + b;
}
__device__ __forceinline__ unsigned long long ffma2(unsigned long long a,
                                                    unsigned long long b,
                                                    unsigned long long c) {
    unsigned long long d;
    asm("fma.rn.f32x2 %0, %1, %2, %3;" : "=l"(d) : "l"(a), "l"(b), "l"(c));
    return d;
}
__device__ __forceinline__ unsigned smem_u32(const void* p) {
    return (unsigned)__cvta_generic_to_shared(p);
}
__device__ __forceinline__ void mbar_init(unsigned addr, unsigned count) {
    asm volatile("mbarrier.init.shared.b64 [%0], %1;" :: "r"(addr), "r"(count) : "memory");
}
__device__ __forceinline__ void mbar_wait_cluster(unsigned addr, unsigned parity) {
    unsigned done;
    do {
        asm volatile(
            "{\n\t.reg .pred p;\n\t"
            "mbarrier.try_wait.parity.acquire.cluster.shared::cta.b64 p, [%1], %2, 0x989680;\n\t"
            "selp.b32 %0, 1, 0, p;\n\t}"
            : "=r"(done) : "r"(addr), "r"(parity) : "memory");
    } while (!done);
}
__device__ __forceinline__ unsigned cluster_rank() {
    unsigned r;
    asm("mov.u32 %0, %%cluster_ctarank;" : "=r"(r));
    return r;
}
__device__ __forceinline__ unsigned mapa_u32(unsigned addr, unsigned rank) {
    unsigned rem;
    asm("mapa.shared::cluster.u32 %0, %1, %2;" : "=r"(rem) : "r"(addr), "r"(rank));
    return rem;
}
__device__ __forceinline__ void st_cluster_v4(unsigned addr, float4 v) {
    asm volatile("st.shared::cluster.v4.f32 [%0], {%1, %2, %3, %4};"
                 :: "r"(addr), "f"(v.x), "f"(v.y), "f"(v.z), "f"(v.w) : "memory");
}
__device__ __forceinline__ void mbar_arrive_remote(unsigned addr) {
    asm volatile("mbarrier.arrive.shared::cluster.b64 _, [%0];" :: "r"(addr) : "memory");
}
__device__ __forceinline__ void cluster_sync() {
    asm volatile("barrier.cluster.arrive.aligned;" ::: "memory");
    asm volatile("barrier.cluster.wait.aligned;" ::: "memory");
}
__device__ __forceinline__ float fsigmoid(float x) {
    return __fdividef(1.f, 1.f + __expf(-x));
}
__device__ __forceinline__ float ftanh_fast(float x) {
    return __fdividef(2.f, 1.f + __expf(-2.f * x)) - 1.f;
}

// ---------------- kernel 1: embedding sums -> X -------------------------------
__global__ void embed_kernel(const int* __restrict__ orig,
                             const int* __restrict__ reply,
                             const int* __restrict__ lens,
                             const float* __restrict__ embed) {
    int t = blockIdx.x;
    int e = threadIdx.x;
    if (e >= E) return;
    float acc = 0.f;
    if (t == 0) {
        #pragma unroll 4
        for (int l = 0; l < L0; ++l) {
            int tok = orig[l];
            acc += embed[(long long)tok * E + e];
        }
    } else {
        int r = t - 1;
        int len = lens[r];
        const int* rt = reply + r * LR;
        #pragma unroll 4
        for (int l = 0; l < len; ++l) {
            int tok = rt[l];
            acc += embed[(long long)tok * E + e];
        }
    }
    g_X[t * E + e] = acc;
}

// ---------------- kernel 2: gi GEMMs (both directions) ------------------------
#define TT 32
#define RR 64
#define KC 32
__global__ void gi_kernel(const float* __restrict__ Wf, const float* __restrict__ bf,
                          const float* __restrict__ Wb, const float* __restrict__ bb) {
    int dir = blockIdx.z;
    const float* W    = dir ? Wb : Wf;
    const float* bias = dir ? bb : bf;
    float* out        = dir ? g_gi_b : g_gi_f;
    int t0 = blockIdx.x * TT;
    int r0 = blockIdx.y * RR;

    __shared__ float Xs[TT][KC];
    __shared__ float Ws[RR][KC + 1];

    int tid = threadIdx.x;
    int r  = tid % RR;
    int tg = tid / RR;

    float acc[8];
    #pragma unroll
    for (int j = 0; j < 8; ++j) acc[j] = 0.f;

    for (int kk = 0; kk < E; kk += KC) {
        for (int i = tid; i < RR * KC; i += 256) {
            int rr = i / KC, k = i % KC;
            Ws[rr][k] = (kk + k < E) ? W[(r0 + rr) * E + kk + k] : 0.f;
        }
        for (int i = tid; i < TT * KC; i += 256) {
            int ttl = i / KC, k = i % KC;
            int t = t0 + ttl;
            float v = 0.f;
            if (t < S && kk + k < E) {
                int tsrc = dir ? (S - 1 - t) : t;
                v = g_X[tsrc * E + kk + k];
            }
            Xs[ttl][k] = v;
        }
        __syncthreads();
        #pragma unroll
        for (int k = 0; k < KC; ++k) {
            float wv = Ws[r][k];
            #pragma unroll
            for (int j = 0; j < 8; ++j)
                acc[j] += wv * Xs[tg * 8 + j][k];
        }
        __syncthreads();
    }
    float bv = bias[r0 + r];
    #pragma unroll
    for (int j = 0; j < 8; ++j) {
        int t = t0 + tg * 8 + j;
        if (t < S) out[t * G3 + r0 + r] = acc[j] + bv;
    }
}

// ---------------- kernel 3: GRU recurrence, cluster(8) per direction ----------
// CTA (rank c) owns h-dims [c*32, c*32+32) -> 96 Whh rows register-resident.
// Warp w handles rows lr = 4w..4w+3 (lr: gate = lr>>5, j = lr&31).
// Lane l holds W[row, 8l..8l+8) packed as 4 f32x2 per row.
// Per step: mbarrier wait (cluster-scope acquire) -> dot (fma.rn.f32x2) ->
// 6-shuffle tree reduce -> gates (warp 0) -> DSMEM publish of 32 h values to
// all 8 CTAs + remote mbarrier arrive. Double-buffered h, per-barrier parity.
__global__ void __launch_bounds__(768, 1) __cluster_dims__(NC, 1, 1)
gru_kernel(const float* __restrict__ Whh_f, const float* __restrict__ bhh_f,
           const float* __restrict__ Whh_b, const float* __restrict__ bhh_b) {
    int dir = blockIdx.x >> 3;
    unsigned c = cluster_rank();
    const float* Whh = dir ? Whh_b : Whh_f;
    const float* bhh = dir ? bhh_b : bhh_f;
    const float* gi  = dir ? g_gi_b : g_gi_f;
    float* ys        = dir ? g_ys_b : g_ys_f;

    int tid  = threadIdx.x;
    int w    = tid >> 5;
    int lane = tid & 31;
    int base = (int)c * DPC;

    __shared__ __align__(16) float hbuf[2][H];   // double-buffered full h
    __shared__ float s_gh[96];
    __shared__ __align__(16) float stage[DPC];
    __shared__ __align__(8) unsigned long long bars[2];

    unsigned hbuf_u32 = smem_u32(&hbuf[0][0]);
    unsigned bars_u32 = smem_u32(&bars[0]);

    // init
    if (tid == 0) { mbar_init(bars_u32, NC); mbar_init(bars_u32 + 8, NC); }
    if (tid < H) hbuf[0][tid] = 0.f;
    __syncthreads();
    cluster_sync();    // peers must not arrive on an uninitialized mbarrier

    // resident weights (4 rows x 8 cols per lane, packed f32x2)
    unsigned long long w2[4][4];
    #pragma unroll
    for (int q = 0; q < 4; ++q) {
        int lr = w * 4 + q;
        int row = (lr >> 5) * H + base + (lr & 31);
        const float* wr = Whh + (size_t)row * H + lane * 8;
        float4 a = *(const float4*)wr;
        float4 b = *(const float4*)(wr + 4);
        w2[q][0] = pk2(a.x, a.y); w2[q][1] = pk2(a.z, a.w);
        w2[q][2] = pk2(b.x, b.y); w2[q][3] = pk2(b.z, b.w);
    }

    // gate-thread residents
    float bhr = 0.f, bhz = 0.f, bhn = 0.f, hold = 0.f;
    float gir = 0.f, giz = 0.f, gin = 0.f;          // gi for current step
    if (tid < DPC) {
        int ii = base + tid;
        bhr = bhh[ii]; bhz = bhh[H + ii]; bhn = bhh[2 * H + ii];
        gir = gi[ii]; giz = gi[H + ii]; gin = gi[2 * H + ii];  // step 0
    }

    unsigned ph0 = 0, ph1 = 0;

    for (int t = 0; t < S; ++t) {
        // prefetch gi for step t+1 (hidden under dot+wait)
        float ngr = 0.f, ngz = 0.f, ngn = 0.f;
        if (tid < DPC && t + 1 < S) {
            const float* gp = gi + (t + 1) * G3 + base + tid;
            ngr = __ldg(gp); ngz = __ldg(gp + H); ngn = __ldg(gp + 2 * H);
        }

        // wait for h_t (written remotely into hbuf[t&1]); t=0 uses zeros
        if (t) {
            if (t & 1) { mbar_wait_cluster(bars_u32 + 8, ph1); ph1 ^= 1; }
            else       { mbar_wait_cluster(bars_u32,     ph0); ph0 ^= 1; }
        }

        // dot: 4 rows x 8 cols per lane using packed f32x2
        const float* hp = &hbuf[t & 1][lane * 8];
        float4 hx = *(const float4*)hp;
        float4 hy = *(const float4*)(hp + 4);
        unsigned long long h2[4];
        h2[0] = pk2(hx.x, hx.y); h2[1] = pk2(hx.z, hx.w);
        h2[2] = pk2(hy.x, hy.y); h2[3] = pk2(hy.z, hy.w);

        float rs[4];
        #pragma unroll
        for (int q = 0; q < 4; ++q) {
            unsigned long long acc = ffma2(w2[q][0], h2[0], 0ULL);
            acc = ffma2(w2[q][1], h2[1], acc);
            acc = ffma2(w2[q][2], h2[2], acc);
            acc = ffma2(w2[q][3], h2[3], acc);
            rs[q] = unpk_sum(acc);
        }

        // 6-shuffle reduce: lane (l&3) ends with full sum of row 4w+(l&3)
        {
            const unsigned FM = 0xffffffffu;
            float as = (lane & 1) ? rs[0] : rs[1];
            float a  = ((lane & 1) ? rs[1] : rs[0]) + __shfl_xor_sync(FM, as, 1);
            float bs = (lane & 1) ? rs[2] : rs[3];
            float b  = ((lane & 1) ? rs[3] : rs[2]) + __shfl_xor_sync(FM, bs, 1);
            float cs = (lane & 2) ? a : b;
            float cc = ((lane & 2) ? b : a) + __shfl_xor_sync(FM, cs, 2);
            cc += __shfl_xor_sync(FM, cc, 4);
            cc += __shfl_xor_sync(FM, cc, 8);
            cc += __shfl_xor_sync(FM, cc, 16);
            if (lane < 4) s_gh[w * 4 + lane] = cc;
        }
        __syncthreads();

        // gates on warp 0 (thread j handles dim base+j)
        if (tid < DPC) {
            float ghr = s_gh[tid] + bhr;
            float ghz = s_gh[32 + tid] + bhz;
            float ghn = s_gh[64 + tid] + bhn;
            float rr = fsigmoid(gir + ghr);
            float zz = fsigmoid(giz + ghz);
            float nn = ftanh_fast(gin + rr * ghn);
            float hn = (1.f - zz) * nn + zz * hold;
            hold = hn;
            int trow = dir ? (S - 1 - t) : t;
            ys[trow * H + base + tid] = hn;
            stage[tid] = hn;
            __syncwarp();

            // publish h_{t+1} to all 8 CTAs' hbuf[(t+1)&1] + arrive
            if (lane < NC && t + 1 < S) {
                unsigned dstb = (unsigned)((t + 1) & 1);
                unsigned dst_local = hbuf_u32 + dstb * (H * 4) + base * 4;
                unsigned rem = mapa_u32(dst_local, lane);
                #pragma unroll
                for (int q = 0; q < 8; ++q) {
                    float4 v = *(const float4*)&stage[q * 4];
                    st_cluster_v4(rem + q * 16, v);
                }
                unsigned remb = mapa_u32(bars_u32 + dstb * 8, lane);
                mbar_arrive_remote(remb);
            }
        }

        gir = ngr; giz = ngz; gin = ngn;
    }
    cluster_sync();
}

// ---------------- kernel 4: output projection --------------------------------
__global__ void outproj_kernel(const float* __restrict__ Wl,
                               const float* __restrict__ bl,
                               float* __restrict__ outbuf) {
    int t0 = blockIdx.x * TT;
    int j0 = blockIdx.y * RR;
    __shared__ float As[TT][KC];
    __shared__ float Ws[RR][KC + 1];
    int tid = threadIdx.x;
    int r  = tid % RR;
    int tg = tid / RR;
    float acc[8];
    #pragma unroll
    for (int j = 0; j < 8; ++j) acc[j] = 0.f;

    for (int kk = 0; kk < 2 * H; kk += KC) {
        const float* ysrc = (kk < H) ? g_ys_f : g_ys_b;
        int kbase = (kk < H) ? kk : (kk - H);
        for (int i = tid; i < RR * KC; i += 256) {
            int rr = i / KC, k = i % KC;
            Ws[rr][k] = Wl[(j0 + rr) * (2 * H) + kk + k];
        }
        for (int i = tid; i < TT * KC; i += 256) {
            int ttl = i / KC, k = i % KC;
            int t = t0 + ttl;
            As[ttl][k] = (t < S) ? ysrc[t * H + kbase + k] : 0.f;
        }
        __syncthreads();
        #pragma unroll
        for (int k = 0; k < KC; ++k) {
            float wv = Ws[r][k];
            #pragma unroll
            for (int j = 0; j < 8; ++j)
                acc[j] += wv * As[tg * 8 + j][k];
        }
        __syncthreads();
    }
    float bv = bl[j0 + r];
    #pragma unroll
    for (int j = 0; j < 8; ++j) {
        int t = t0 + tg * 8 + j;
        if (t < S) outbuf[t * H + j0 + r] = acc[j] + bv;
    }
}

// ---------------- kernel 5: attention + final head (single block) -------------
__global__ void attn_kernel(const float* __restrict__ outbuf,
                            const float* __restrict__ Wo,
                            const float* __restrict__ bo,
                            const float* __restrict__ label,
                            float* __restrict__ tail) {
    __shared__ float s_hsum[H];
    __shared__ float s_w[S];
    __shared__ float s_red[32];
    __shared__ float s_ctx[4][H];

    int tid = threadIdx.x;
    int wp  = tid >> 5;
    int ln  = tid & 31;

    if (tid < H) s_hsum[tid] = g_ys_f[(S - 1) * H + tid] + g_ys_b[tid];
    __syncthreads();

    for (int t = wp; t < S; t += 32) {
        const float* o = outbuf + t * H;
        float s = 0.f;
        #pragma unroll
        for (int k = ln; k < H; k += 32) s += o[k] * s_hsum[k];
        s += __shfl_down_sync(0xffffffffu, s, 16);
        s += __shfl_down_sync(0xffffffffu, s, 8);
        s += __shfl_down_sync(0xffffffffu, s, 4);
        s += __shfl_down_sync(0xffffffffu, s, 2);
        s += __shfl_down_sync(0xffffffffu, s, 1);
        if (ln == 0) s_w[t] = s;
    }
    __syncthreads();

    float m = -CUDART_INF_F;
    for (int t = tid; t < S; t += 1024) m = fmaxf(m, s_w[t]);
    for (int off = 16; off >= 1; off >>= 1)
        m = fmaxf(m, __shfl_down_sync(0xffffffffu, m, off));
    if (ln == 0) s_red[wp] = m;
    __syncthreads();
    if (tid < 32) {
        float mm = s_red[tid];
        for (int off = 16; off >= 1; off >>= 1)
            mm = fmaxf(mm, __shfl_down_sync(0xffffffffu, mm, off));
        if (tid == 0) s_red[0] = mm;
    }
    __syncthreads();
    float M = s_red[0];
    __syncthreads();

    float lsum = 0.f;
    for (int t = tid; t < S; t += 1024) {
        float e = expf(s_w[t] - M);
        s_w[t] = e;
        lsum += e;
    }
    for (int off = 16; off >= 1; off >>= 1)
        lsum += __shfl_down_sync(0xffffffffu, lsum, off);
    if (ln == 0) s_red[wp] = lsum;
    __syncthreads();
    if (tid < 32) {
        float ss = s_red[tid];
        for (int off = 16; off >= 1; off >>= 1)
            ss += __shfl_down_sync(0xffffffffu, ss, off);
        if (tid == 0) s_red[0] = ss;
    }
    __syncthreads();
    float SUM = s_red[0];

    int j    = tid & 255;
    int part = tid >> 8;
    float cacc = 0.f;
    #pragma unroll 4
    for (int t = part; t < S; t += 4) cacc += s_w[t] * outbuf[t * H + j];
    s_ctx[part][j] = cacc;
    __syncthreads();

    if (tid < H) {
        float cj = (s_ctx[0][tid] + s_ctx[1][tid] + s_ctx[2][tid] + s_ctx[3][tid]) / SUM;
        s_hsum[tid] = cj * Wo[tid];
    }
    __syncthreads();

    if (tid < 32) {
        float a = 0.f;
        #pragma unroll
        for (int q = 0; q < 8; ++q) a += s_hsum[tid + q * 32];
        for (int off = 16; off >= 1; off >>= 1)
            a += __shfl_down_sync(0xffffffffu, a, off);
        if (tid == 0) {
            float res = 1.f / (1.f + expf(-(a + bo[0])));
            float d = label[0] - res;
            tail[0] = d * d;
            tail[1] = res;
        }
    }
}

// ---------------- launch ------------------------------------------------------
extern "C" void kernel_launch(void* const* d_in, const int* in_sizes, int n_in,
                              void* d_out, int out_size) {
    const int*   orig   = (const int*)d_in[0];
    const int*   reply  = (const int*)d_in[1];
    const int*   lens   = (const int*)d_in[2];
    const float* label  = (const float*)d_in[3];
    const float* embed  = (const float*)d_in[4];
    const float* Wih_f  = (const float*)d_in[5];
    const float* Whh_f  = (const float*)d_in[6];
    const float* bih_f  = (const float*)d_in[7];
    const float* bhh_f  = (const float*)d_in[8];
    const float* Wih_b  = (const float*)d_in[9];
    const float* Whh_b  = (const float*)d_in[10];
    const float* bih_b  = (const float*)d_in[11];
    const float* bhh_b  = (const float*)d_in[12];
    const float* Wl     = (const float*)d_in[13];
    const float* bl     = (const float*)d_in[14];
    const float* Wo     = (const float*)d_in[15];
    const float* bo     = (const float*)d_in[16];
    float* out = (float*)d_out;

    embed_kernel<<<S, 320>>>(orig, reply, lens, embed);

    dim3 gi_grid((S + TT - 1) / TT, G3 / RR, 2);
    gi_kernel<<<gi_grid, 256>>>(Wih_f, bih_f, Wih_b, bih_b);

    gru_kernel<<<2 * NC, 768>>>(Whh_f, bhh_f, Whh_b, bhh_b);

    dim3 op_grid((S + TT - 1) / TT, H / RR);
    outproj_kernel<<<op_grid, 256>>>(Wl, bl, out);

    attn_kernel<<<1, 1024>>>(out, Wo, bo, label, out + S * H);
}

// round 4
// speedup vs baseline: 2.4076x; 1.1867x over previous
#include <cuda_runtime.h>
#include <math_constants.h>

#define V  50000
#define E  300
#define H  256
#define R  2048
#define L0 128
#define LR 64
#define S  2049          // 1 + R
#define G3 768           // 3*H

#define NC     8         // CTAs per cluster (one cluster per direction)
#define DPC    32        // h-dims per CTA
#define GRU_T  384       // threads per gru CTA (12 warps x 8 rows = 96 rows)

// ---------------- scratch (device globals; no allocation allowed) -------------
__device__ float g_X[S * E];
__device__ float g_gi_f[S * G3];
__device__ float g_gi_b[S * G3];
__device__ float g_ys_f[S * H];
__device__ float g_ys_b[S * H];

// ---------------- small PTX helpers ------------------------------------------
__device__ __forceinline__ unsigned long long pk2(float lo, float hi) {
    unsigned long long r;
    asm("mov.b64 %0, {%1, %2};" : "=l"(r) : "f"(lo), "f"(hi));
    return r;
}
__device__ __forceinline__ float unpk_sum(unsigned long long v) {
    float a, b;
    asm("mov.b64 {%0, %1}, %2;" : "=f"(a), "=f"(b) : "l"(v));
    return a + b;
}
__device__ __forceinline__ unsigned long long ffma2(unsigned long long a,
                                                    unsigned long long b,
                                                    unsigned long long c) {
    unsigned long long d;
    asm("fma.rn.f32x2 %0, %1, %2, %3;" : "=l"(d) : "l"(a), "l"(b), "l"(c));
    return d;
}
__device__ __forceinline__ unsigned smem_u32(const void* p) {
    return (unsigned)__cvta_generic_to_shared(p);
}
__device__ __forceinline__ void mbar_init(unsigned addr, unsigned count) {
    asm volatile("mbarrier.init.shared.b64 [%0], %1;" :: "r"(addr), "r"(count) : "memory");
}
__device__ __forceinline__ void mbar_wait_cluster(unsigned addr, unsigned parity) {
    unsigned done;
    do {
        asm volatile(
            "{\n\t.reg .pred p;\n\t"
            "mbarrier.try_wait.parity.acquire.cluster.shared::cta.b64 p, [%1], %2, 0x989680;\n\t"
            "selp.b32 %0, 1, 0, p;\n\t}"
            : "=r"(done) : "r"(addr), "r"(parity) : "memory");
    } while (!done);
}
__device__ __forceinline__ unsigned cluster_rank() {
    unsigned r;
    asm("mov.u32 %0, %%cluster_ctarank;" : "=r"(r));
    return r;
}
__device__ __forceinline__ unsigned mapa_u32(unsigned addr, unsigned rank) {
    unsigned rem;
    asm("mapa.shared::cluster.u32 %0, %1, %2;" : "=r"(rem) : "r"(addr), "r"(rank));
    return rem;
}
__device__ __forceinline__ void st_cluster_f32(unsigned addr, float v) {
    asm volatile("st.shared::cluster.f32 [%0], %1;" :: "r"(addr), "f"(v) : "memory");
}
__device__ __forceinline__ void mbar_arrive_remote(unsigned addr) {
    asm volatile("mbarrier.arrive.shared::cluster.b64 _, [%0];" :: "r"(addr) : "memory");
}
__device__ __forceinline__ void cluster_sync() {
    asm volatile("barrier.cluster.arrive.aligned;" ::: "memory");
    asm volatile("barrier.cluster.wait.aligned;" ::: "memory");
}
__device__ __forceinline__ void bar_arrive_1() {
    asm volatile("bar.arrive 1, %0;" :: "r"(GRU_T) : "memory");
}
__device__ __forceinline__ void bar_sync_1() {
    asm volatile("bar.sync 1, %0;" :: "r"(GRU_T) : "memory");
}
__device__ __forceinline__ float fsigmoid(float x) {
    return __fdividef(1.f, 1.f + __expf(-x));
}
__device__ __forceinline__ float ftanh_fast(float x) {
    return __fdividef(2.f, 1.f + __expf(-2.f * x)) - 1.f;
}

// ---------------- kernel 1: embedding sums -> X -------------------------------
__global__ void embed_kernel(const int* __restrict__ orig,
                             const int* __restrict__ reply,
                             const int* __restrict__ lens,
                             const float* __restrict__ embed) {
    int t = blockIdx.x;
    int e = threadIdx.x;
    if (e >= E) return;
    float acc = 0.f;
    if (t == 0) {
        #pragma unroll 4
        for (int l = 0; l < L0; ++l) {
            int tok = orig[l];
            acc += embed[(long long)tok * E + e];
        }
    } else {
        int r = t - 1;
        int len = lens[r];
        const int* rt = reply + r * LR;
        #pragma unroll 4
        for (int l = 0; l < len; ++l) {
            int tok = rt[l];
            acc += embed[(long long)tok * E + e];
        }
    }
    g_X[t * E + e] = acc;
}

// ---------------- kernel 2: gi GEMMs (both directions) ------------------------
#define TT 32
#define RR 64
#define KC 32
__global__ void gi_kernel(const float* __restrict__ Wf, const float* __restrict__ bf,
                          const float* __restrict__ Wb, const float* __restrict__ bb) {
    int dir = blockIdx.z;
    const float* W    = dir ? Wb : Wf;
    const float* bias = dir ? bb : bf;
    float* out        = dir ? g_gi_b : g_gi_f;
    int t0 = blockIdx.x * TT;
    int r0 = blockIdx.y * RR;

    __shared__ float Xs[TT][KC];
    __shared__ float Ws[RR][KC + 1];

    int tid = threadIdx.x;
    int r  = tid % RR;
    int tg = tid / RR;

    float acc[8];
    #pragma unroll
    for (int j = 0; j < 8; ++j) acc[j] = 0.f;

    for (int kk = 0; kk < E; kk += KC) {
        for (int i = tid; i < RR * KC; i += 256) {
            int rr = i / KC, k = i % KC;
            Ws[rr][k] = (kk + k < E) ? W[(r0 + rr) * E + kk + k] : 0.f;
        }
        for (int i = tid; i < TT * KC; i += 256) {
            int ttl = i / KC, k = i % KC;
            int t = t0 + ttl;
            float v = 0.f;
            if (t < S && kk + k < E) {
                int tsrc = dir ? (S - 1 - t) : t;
                v = g_X[tsrc * E + kk + k];
            }
            Xs[ttl][k] = v;
        }
        __syncthreads();
        #pragma unroll
        for (int k = 0; k < KC; ++k) {
            float wv = Ws[r][k];
            #pragma unroll
            for (int j = 0; j < 8; ++j)
                acc[j] += wv * Xs[tg * 8 + j][k];
        }
        __syncthreads();
    }
    float bv = bias[r0 + r];
    #pragma unroll
    for (int j = 0; j < 8; ++j) {
        int t = t0 + tg * 8 + j;
        if (t < S) out[t * G3 + r0 + r] = acc[j] + bv;
    }
}

// ---------------- kernel 3: GRU recurrence, cluster(8) per direction ----------
// 12 warps/CTA; warp w owns local rows 8w..8w+7 (lr: gate = lr>>5, dim = lr&31).
// Lane holds 8 rows x 8 cols (cols lane*8..+8) register-resident, packed f32x2.
// Per step: mbar wait -> 1 KB h LDS (per warp) -> 32 ffma2 -> 9-shuffle fold
// reduce -> lane<8 STS row sums (+bias) -> bar.arrive (warps 1-11) /
// bar.sync (warp 0) -> warp0: gates per lane(dim) -> register-direct DSMEM
// publish to 8 peers -> remote mbarrier arrives. Double-buffered h + parity.
__global__ void __launch_bounds__(GRU_T, 1) __cluster_dims__(NC, 1, 1)
gru_kernel(const float* __restrict__ Whh_f, const float* __restrict__ bhh_f,
           const float* __restrict__ Whh_b, const float* __restrict__ bhh_b) {
    int dir = blockIdx.x >> 3;
    unsigned c = cluster_rank();
    const float* Whh = dir ? Whh_b : Whh_f;
    const float* bhh = dir ? bhh_b : bhh_f;
    const float* gi  = dir ? g_gi_b : g_gi_f;
    float* ys        = dir ? g_ys_b : g_ys_f;

    int tid  = threadIdx.x;
    int w    = tid >> 5;        // 0..11
    int lane = tid & 31;
    int base = (int)c * DPC;

    __shared__ __align__(16) float hbuf[2][H];   // double-buffered full h
    __shared__ float s_gh[96];                   // row sums incl. bhh
    __shared__ __align__(8) unsigned long long bars[2];

    unsigned hbuf_u32 = smem_u32(&hbuf[0][0]);
    unsigned bars_u32 = smem_u32(&bars[0]);

    if (tid == 0) { mbar_init(bars_u32, NC); mbar_init(bars_u32 + 8, NC); }
    if (tid < H) hbuf[0][tid] = 0.f;
    __syncthreads();
    cluster_sync();   // peers must not arrive on an uninitialized mbarrier

    // precomputed remote addresses (used by warp 0)
    unsigned remh[NC], remb[NC];
    #pragma unroll
    for (int r = 0; r < NC; ++r) {
        remh[r] = mapa_u32(hbuf_u32, (unsigned)r);
        remb[r] = mapa_u32(bars_u32, (unsigned)r);
    }

    // resident weights: 8 rows x 8 cols per lane, packed f32x2
    unsigned long long w2[8][4];
    #pragma unroll
    for (int k = 0; k < 8; ++k) {
        int lr = w * 8 + k;
        int row = (lr >> 5) * H + base + (lr & 31);
        const float* wr = Whh + (size_t)row * H + lane * 8;
        float4 a = *(const float4*)wr;
        float4 b = *(const float4*)(wr + 4);
        w2[k][0] = pk2(a.x, a.y); w2[k][1] = pk2(a.z, a.w);
        w2[k][2] = pk2(b.x, b.y); w2[k][3] = pk2(b.z, b.w);
    }
    // bias for the row this lane will end up owning after the fold reduce
    float breg;
    {
        int lrb = w * 8 + (lane & 7);
        int rowb = (lrb >> 5) * H + base + (lrb & 31);
        breg = bhh[rowb];
    }

    // warp0 per-lane gate state (lane = local dim)
    float bn_r = 0.f, gir = 0.f, giz = 0.f, gin = 0.f, hold = 0.f;
    (void)bn_r;
    if (w == 0) {
        int ii = base + lane;
        gir = gi[ii]; giz = gi[H + ii]; gin = gi[2 * H + ii];   // step 0
    }

    unsigned ph0 = 0, ph1 = 0;
    const unsigned FM = 0xffffffffu;

    for (int t = 0; t < S; ++t) {
        // prefetch gi for step t+1 (warp 0 only; hidden under dot+wait)
        float ngr = 0.f, ngz = 0.f, ngn = 0.f;
        if (w == 0 && t + 1 < S) {
            const float* gp = gi + (t + 1) * G3 + base + lane;
            ngr = __ldg(gp); ngz = __ldg(gp + H); ngn = __ldg(gp + 2 * H);
        }

        // wait for h_t in hbuf[t&1]; t=0 uses zeros
        if (t) {
            if (t & 1) { mbar_wait_cluster(bars_u32 + 8, ph1); ph1 ^= 1; }
            else       { mbar_wait_cluster(bars_u32,     ph0); ph0 ^= 1; }
        }

        // dot: 8 rows x 8 cols per lane
        const float4* hp = (const float4*)(&hbuf[t & 1][lane * 8]);
        float4 hx = hp[0];
        float4 hy = hp[1];
        unsigned long long h2[4];
        h2[0] = pk2(hx.x, hx.y); h2[1] = pk2(hx.z, hx.w);
        h2[2] = pk2(hy.x, hy.y); h2[3] = pk2(hy.z, hy.w);

        float p[8];
        #pragma unroll
        for (int k = 0; k < 8; ++k) {
            unsigned long long acc = ffma2(w2[k][0], h2[0], 0ULL);
            acc = ffma2(w2[k][1], h2[1], acc);
            acc = ffma2(w2[k][2], h2[2], acc);
            acc = ffma2(w2[k][3], h2[3], acc);
            p[k] = unpk_sum(acc);
        }

        // fold reduce: 8 values over 32 lanes -> lane l<8 holds row 8w+l
        bool b0 = (lane & 1), b1 = (lane & 2), b2 = (lane & 4);
        float q0, q1, q2, q3, r0v, r1v, u;
        { float v = b0 ? p[0] : p[1]; float sx = __shfl_xor_sync(FM, v, 1);
          q0 = (b0 ? p[1] : p[0]) + sx; }
        { float v = b0 ? p[2] : p[3]; float sx = __shfl_xor_sync(FM, v, 1);
          q1 = (b0 ? p[3] : p[2]) + sx; }
        { float v = b0 ? p[4] : p[5]; float sx = __shfl_xor_sync(FM, v, 1);
          q2 = (b0 ? p[5] : p[4]) + sx; }
        { float v = b0 ? p[6] : p[7]; float sx = __shfl_xor_sync(FM, v, 1);
          q3 = (b0 ? p[7] : p[6]) + sx; }
        { float v = b1 ? q0 : q1; float sx = __shfl_xor_sync(FM, v, 2);
          r0v = (b1 ? q1 : q0) + sx; }
        { float v = b1 ? q2 : q3; float sx = __shfl_xor_sync(FM, v, 2);
          r1v = (b1 ? q3 : q2) + sx; }
        { float v = b2 ? r0v : r1v; float sx = __shfl_xor_sync(FM, v, 4);
          u = (b2 ? r1v : r0v) + sx; }
        u += __shfl_xor_sync(FM, u, 8);
        u += __shfl_xor_sync(FM, u, 16);
        if (lane < 8) s_gh[w * 8 + lane] = u + breg;   // gh row incl. bias

        if (w != 0) {
            bar_arrive_1();        // non-blocking; next stop: mbar wait t+1
        } else {
            bar_sync_1();          // wait for all 12 warps' STS (BAR drains STS)
            // gates: lane = local dim
            float ghr = s_gh[lane];
            float ghz = s_gh[32 + lane];
            float ghn = s_gh[64 + lane];
            float rr = fsigmoid(gir + ghr);
            float zz = fsigmoid(giz + ghz);
            float nn = ftanh_fast(gin + rr * ghn);
            float hn = (1.f - zz) * nn + zz * hold;
            hold = hn;

            // publish h_{t+1} to all 8 CTAs (register-direct DSMEM stores)
            if (t + 1 < S) {
                unsigned off = (unsigned)(((t + 1) & 1) * (H * 4) + (base + lane) * 4);
                #pragma unroll
                for (int r = 0; r < NC; ++r)
                    st_cluster_f32(remh[r] + off, hn);
                __syncwarp();
                if (lane < NC)
                    mbar_arrive_remote(remb[lane] + ((t + 1) & 1) * 8);
            }

            int trow = dir ? (S - 1 - t) : t;
            ys[trow * H + base + lane] = hn;
            gir = ngr; giz = ngz; gin = ngn;
        }
    }
    cluster_sync();
}

// ---------------- kernel 4: output projection --------------------------------
#define OTT 16
__global__ void outproj_kernel(const float* __restrict__ Wl,
                               const float* __restrict__ bl,
                               float* __restrict__ outbuf) {
    int t0 = blockIdx.x * OTT;
    int j0 = blockIdx.y * RR;
    __shared__ float As[OTT][KC];
    __shared__ float Ws[RR][KC + 1];
    int tid = threadIdx.x;
    int r  = tid % RR;
    int tg = tid / RR;     // 0..3, each handles 4 t's
    float acc[4];
    #pragma unroll
    for (int j = 0; j < 4; ++j) acc[j] = 0.f;

    for (int kk = 0; kk < 2 * H; kk += KC) {
        const float* ysrc = (kk < H) ? g_ys_f : g_ys_b;
        int kbase = (kk < H) ? kk : (kk - H);
        for (int i = tid; i < RR * KC; i += 256) {
            int rr = i / KC, k = i % KC;
            Ws[rr][k] = Wl[(j0 + rr) * (2 * H) + kk + k];
        }
        for (int i = tid; i < OTT * KC; i += 256) {
            int ttl = i / KC, k = i % KC;
            int t = t0 + ttl;
            As[ttl][k] = (t < S) ? ysrc[t * H + kbase + k] : 0.f;
        }
        __syncthreads();
        #pragma unroll
        for (int k = 0; k < KC; ++k) {
            float wv = Ws[r][k];
            #pragma unroll
            for (int j = 0; j < 4; ++j)
                acc[j] += wv * As[tg * 4 + j][k];
        }
        __syncthreads();
    }
    float bv = bl[j0 + r];
    #pragma unroll
    for (int j = 0; j < 4; ++j) {
        int t = t0 + tg * 4 + j;
        if (t < S) outbuf[t * H + j0 + r] = acc[j] + bv;
    }
}

// ---------------- kernel 5: attention + final head (single block) -------------
__global__ void attn_kernel(const float* __restrict__ outbuf,
                            const float* __restrict__ Wo,
                            const float* __restrict__ bo,
                            const float* __restrict__ label,
                            float* __restrict__ tail) {
    __shared__ float s_hsum[H];
    __shared__ float s_w[S];
    __shared__ float s_red[32];
    __shared__ float s_ctx[4][H];

    int tid = threadIdx.x;
    int wp  = tid >> 5;
    int ln  = tid & 31;

    if (tid < H) s_hsum[tid] = g_ys_f[(S - 1) * H + tid] + g_ys_b[tid];
    __syncthreads();

    for (int t = wp; t < S; t += 32) {
        const float* o = outbuf + t * H;
        float s = 0.f;
        #pragma unroll
        for (int k = ln; k < H; k += 32) s += o[k] * s_hsum[k];
        s += __shfl_down_sync(0xffffffffu, s, 16);
        s += __shfl_down_sync(0xffffffffu, s, 8);
        s += __shfl_down_sync(0xffffffffu, s, 4);
        s += __shfl_down_sync(0xffffffffu, s, 2);
        s += __shfl_down_sync(0xffffffffu, s, 1);
        if (ln == 0) s_w[t] = s;
    }
    __syncthreads();

    float m = -CUDART_INF_F;
    for (int t = tid; t < S; t += 1024) m = fmaxf(m, s_w[t]);
    for (int off = 16; off >= 1; off >>= 1)
        m = fmaxf(m, __shfl_down_sync(0xffffffffu, m, off));
    if (ln == 0) s_red[wp] = m;
    __syncthreads();
    if (tid < 32) {
        float mm = s_red[tid];
        for (int off = 16; off >= 1; off >>= 1)
            mm = fmaxf(mm, __shfl_down_sync(0xffffffffu, mm, off));
        if (tid == 0) s_red[0] = mm;
    }
    __syncthreads();
    float M = s_red[0];
    __syncthreads();

    float lsum = 0.f;
    for (int t = tid; t < S; t += 1024) {
        float e = expf(s_w[t] - M);
        s_w[t] = e;
        lsum += e;
    }
    for (int off = 16; off >= 1; off >>= 1)
        lsum += __shfl_down_sync(0xffffffffu, lsum, off);
    if (ln == 0) s_red[wp] = lsum;
    __syncthreads();
    if (tid < 32) {
        float ss = s_red[tid];
        for (int off = 16; off >= 1; off >>= 1)
            ss += __shfl_down_sync(0xffffffffu, ss, off);
        if (tid == 0) s_red[0] = ss;
    }
    __syncthreads();
    float SUM = s_red[0];

    int j    = tid & 255;
    int part = tid >> 8;
    float cacc = 0.f;
    #pragma unroll 4
    for (int t = part; t < S; t += 4) cacc += s_w[t] * outbuf[t * H + j];
    s_ctx[part][j] = cacc;
    __syncthreads();

    if (tid < H) {
        float cj = (s_ctx[0][tid] + s_ctx[1][tid] + s_ctx[2][tid] + s_ctx[3][tid]) / SUM;
        s_hsum[tid] = cj * Wo[tid];
    }
    __syncthreads();

    if (tid < 32) {
        float a = 0.f;
        #pragma unroll
        for (int q = 0; q < 8; ++q) a += s_hsum[tid + q * 32];
        for (int off = 16; off >= 1; off >>= 1)
            a += __shfl_down_sync(0xffffffffu, a, off);
        if (tid == 0) {
            float res = 1.f / (1.f + expf(-(a + bo[0])));
            float d = label[0] - res;
            tail[0] = d * d;
            tail[1] = res;
        }
    }
}

// ---------------- launch ------------------------------------------------------
extern "C" void kernel_launch(void* const* d_in, const int* in_sizes, int n_in,
                              void* d_out, int out_size) {
    const int*   orig   = (const int*)d_in[0];
    const int*   reply  = (const int*)d_in[1];
    const int*   lens   = (const int*)d_in[2];
    const float* label  = (const float*)d_in[3];
    const float* embed  = (const float*)d_in[4];
    const float* Wih_f  = (const float*)d_in[5];
    const float* Whh_f  = (const float*)d_in[6];
    const float* bih_f  = (const float*)d_in[7];
    const float* bhh_f  = (const float*)d_in[8];
    const float* Wih_b  = (const float*)d_in[9];
    const float* Whh_b  = (const float*)d_in[10];
    const float* bih_b  = (const float*)d_in[11];
    const float* bhh_b  = (const float*)d_in[12];
    const float* Wl     = (const float*)d_in[13];
    const float* bl     = (const float*)d_in[14];
    const float* Wo     = (const float*)d_in[15];
    const float* bo     = (const float*)d_in[16];
    float* out = (float*)d_out;

    embed_kernel<<<S, 320>>>(orig, reply, lens, embed);

    dim3 gi_grid((S + TT - 1) / TT, G3 / RR, 2);
    gi_kernel<<<gi_grid, 256>>>(Wih_f, bih_f, Wih_b, bih_b);

    gru_kernel<<<2 * NC, GRU_T>>>(Whh_f, bhh_f, Whh_b, bhh_b);

    dim3 op_grid((S + OTT - 1) / OTT, H / RR);   // 129 x 4
    outproj_kernel<<<op_grid, 256>>>(Wl, bl, out);

    attn_kernel<<<1, 1024>>>(out, Wo, bo, label, out + S * H);
}